// round 1
// baseline (speedup 1.0000x reference)
#include <cuda_runtime.h>
#include <cstdint>

#define Bq 8
#define Lq 256
#define Hq 128
#define BLq 2048
#define HHq 16384

// ---------------- scratch (no allocation allowed) ----------------
__device__ float g_qln[BLq*Hq];
__device__ float g_Q  [BLq*Hq];
__device__ float g_K  [BLq*Hq];
__device__ float g_V  [BLq*Hq];
__device__ float g_u  [BLq*4*Hq];
__device__ float g_att[BLq*Hq];
__device__ float g_y  [BLq*Hq];
__device__ float g_x  [BLq*Hq];

// ---------------- helpers ----------------
__device__ __forceinline__ void cpa16(float* s, const float* g){
    unsigned sa = (unsigned)__cvta_generic_to_shared(s);
    asm volatile("cp.async.cg.shared.global [%0], [%1], 16;\n" :: "r"(sa), "l"(g));
}

// ---------------- layernorm: one row per block, 128 threads ----------------
__global__ void k_ln(const float* __restrict__ x, const float* __restrict__ g,
                     const float* __restrict__ bb, float* __restrict__ y){
    int r = blockIdx.x; int e = threadIdx.x;
    float v = x[(size_t)r*Hq + e];
    float s = v, s2 = v*v;
    #pragma unroll
    for(int o=16;o;o>>=1){
        s  += __shfl_xor_sync(0xffffffffu, s , o);
        s2 += __shfl_xor_sync(0xffffffffu, s2, o);
    }
    __shared__ float sh[8];
    int w = e>>5, l = e&31;
    if(l==0){ sh[w]=s; sh[4+w]=s2; }
    __syncthreads();
    s  = sh[0]+sh[1]+sh[2]+sh[3];
    s2 = sh[4]+sh[5]+sh[6]+sh[7];
    float m   = s * (1.0f/128.0f);
    float var = s2 * (1.0f/128.0f) - m*m;
    y[(size_t)r*Hq + e] = (v - m) * rsqrtf(var + 1e-8f) * g[e] + bb[e];
}

// ---------------- 16-row tiled GEMM helper: out[e] = bias[e] + xs @ W[e,:] ----------------
// 256 threads: e = t&127 (output), s = t>>7 (c-half). All threads must call (has syncthreads).
__device__ __forceinline__ void mat16(const float xs[16][128], float ps[16][128],
                                      const float* __restrict__ W, const float* __restrict__ bias,
                                      int e, int s, float out[16]){
    float acc[16];
    #pragma unroll
    for(int r=0;r<16;r++) acc[r]=0.f;
    const float4* wq = (const float4*)(W + (size_t)e*128 + s*64);
    #pragma unroll
    for(int cq=0;cq<16;cq++){
        float4 wv = wq[cq];
        #pragma unroll
        for(int r=0;r<16;r++){
            float4 xv = *(const float4*)(&xs[r][s*64 + cq*4]);
            acc[r] += wv.x*xv.x + wv.y*xv.y + wv.z*xv.z + wv.w*xv.w;
        }
    }
    if(s==1){
        #pragma unroll
        for(int r=0;r<16;r++) ps[r][e]=acc[r];
    }
    __syncthreads();
    if(s==0){
        float be = bias[e];
        #pragma unroll
        for(int r=0;r<16;r++) out[r] = acc[r] + ps[r][e] + be;
    }
}

// ---------------- projection: Q,K,V rows + per-head u = WA1_h^T Q_h ----------------
__global__ void __launch_bounds__(256) k_proj(
    const float* __restrict__ xin,
    const float* __restrict__ Wq, const float* __restrict__ bq,
    const float* __restrict__ Wk, const float* __restrict__ bk,
    const float* __restrict__ Wv, const float* __restrict__ bv,
    const float* __restrict__ Wa1,
    float* __restrict__ Qo, float* __restrict__ Ko, float* __restrict__ Vo,
    float* __restrict__ uo)
{
    __shared__ float xs[16][128];
    __shared__ float ps[16][128];
    __shared__ float Qs[16][128];
    int t = threadIdx.x; int e = t & 127; int s = t >> 7;
    int r0 = blockIdx.x * 16;
    for(int k=t;k<2048;k+=256) xs[k>>7][k&127] = xin[(size_t)r0*Hq + k];
    __syncthreads();

    float o16[16];
    mat16(xs, ps, Wq, bq, e, s, o16);
    if(s==0){
        #pragma unroll
        for(int r=0;r<16;r++){ float v=o16[r]; Qo[(size_t)(r0+r)*Hq+e]=v; Qs[r][e]=v; }
    }
    __syncthreads();
    mat16(xs, ps, Wk, bk, e, s, o16);
    if(s==0){
        #pragma unroll
        for(int r=0;r<16;r++) Ko[(size_t)(r0+r)*Hq+e]=o16[r];
    }
    __syncthreads();
    mat16(xs, ps, Wv, bv, e, s, o16);
    if(s==0){
        #pragma unroll
        for(int r=0;r<16;r++) Vo[(size_t)(r0+r)*Hq+e]=o16[r];
    }
    __syncthreads();

    // u[row][h][c] = sum_d WA1[h*32+d, c] * Q[row, h*32+d]
    int h = t>>6, c0 = t&63;
    float a0[16], a1[16];
    #pragma unroll
    for(int r=0;r<16;r++){ a0[r]=0.f; a1[r]=0.f; }
    for(int d=0; d<32; d++){
        const float* wr = Wa1 + (size_t)(h*32+d)*128;
        float w0 = wr[c0], w1 = wr[c0+64];
        #pragma unroll
        for(int r=0;r<16;r++){
            float q = Qs[r][h*32+d];
            a0[r] += w0*q; a1[r] += w1*q;
        }
    }
    #pragma unroll
    for(int r=0;r<16;r++){
        size_t base = ((size_t)(r0+r)*4 + h)*128;
        uo[base + c0]      = a0[r];
        uo[base + c0 + 64] = a1[r];
    }
}

// ---------------- fused attention: one CTA per (b,i) query row ----------------
#define ATTN_SMEM ((256*128 + 1024 + 512)*4)
__global__ void __launch_bounds__(256) k_attn(
    const float* __restrict__ tm,  const float* __restrict__ qln,
    const float* __restrict__ Qp,  const float* __restrict__ Kp,
    const float* __restrict__ Vp,  const float* __restrict__ up,
    const unsigned char* __restrict__ msk,
    const float* __restrict__ Wa2, float* __restrict__ xo)
{
    extern __shared__ float sm[];
    float* tm_s = sm;                   // 256*128
    float* sc   = sm + 32768;           // 4*256 scores -> weights
    float* t_s  = sm + 32768 + 1024;    // 4*128

    int t = threadIdx.x, l = t&31, w = t>>5;
    int r = blockIdx.x, b = r>>8, i = r&255;
    bool rowmask = msk[r] != 0;
    int nj  = rowmask ? 256 : (i+1);
    int njq = (nj+3)>>2;

    // stream tm row into smem (only causal rows)
    const float* src = tm + (size_t)r*32768;
    int n4 = nj*32;
    for(int k=t;k<n4;k+=256) cpa16(tm_s + 4*k, src + 4*k);
    asm volatile("cp.async.commit_group;\n"::);
    // zero-pad up to quad boundary (prevents NaN*0 in phase2)
    int padf = (njq*4 - nj)*128;
    for(int k=t;k<padf;k+=256) tm_s[nj*128 + k] = 0.f;

    // preload u-row and Q-row into registers (overlaps with cp.async)
    float4 uv[4]; float qv[4];
    #pragma unroll
    for(int h=0;h<4;h++){
        uv[h] = ((const float4*)(up + (size_t)r*512 + h*128))[l];
        qv[h] = Qp[(size_t)r*128 + h*32 + l];
    }
    asm volatile("cp.async.wait_group 0;\n"::);
    __syncthreads();

    // ---- phase 1: scores[h][j] = Qh.Kh[j] + u_h . tm[j]  (warp per j) ----
    for(int j=w; j<nj; j+=8){
        float4 tv = ((const float4*)(tm_s + j*128))[l];
        const float* Kr = Kp + (((size_t)b<<8) + j)*128;
        float a0 = uv[0].x*tv.x + uv[0].y*tv.y + uv[0].z*tv.z + uv[0].w*tv.w + qv[0]*Kr[l];
        float a1 = uv[1].x*tv.x + uv[1].y*tv.y + uv[1].z*tv.z + uv[1].w*tv.w + qv[1]*Kr[32+l];
        float a2 = uv[2].x*tv.x + uv[2].y*tv.y + uv[2].z*tv.z + uv[2].w*tv.w + qv[2]*Kr[64+l];
        float a3 = uv[3].x*tv.x + uv[3].y*tv.y + uv[3].z*tv.z + uv[3].w*tv.w + qv[3]*Kr[96+l];
        #pragma unroll
        for(int o=16;o;o>>=1){
            a0 += __shfl_xor_sync(0xffffffffu,a0,o);
            a1 += __shfl_xor_sync(0xffffffffu,a1,o);
            a2 += __shfl_xor_sync(0xffffffffu,a2,o);
            a3 += __shfl_xor_sync(0xffffffffu,a3,o);
        }
        if(l<4) sc[l*256 + j] = (l==0)?a0:((l==1)?a1:((l==2)?a2:a3));
    }
    __syncthreads();

    // ---- softmax per head (warp per h) ----
    if(w<4){
        const float NEGV = -4294967295.0f;
        float vals[8]; float mx = -3.4e38f;
        #pragma unroll
        for(int k=0;k<8;k++){
            int j = l + 32*k;
            float sv = sc[w*256+j]*0.17677669529663689f;
            sv = (j < nj && !rowmask) ? sv : NEGV;
            vals[k]=sv; mx = fmaxf(mx, sv);
        }
        #pragma unroll
        for(int o=16;o;o>>=1) mx = fmaxf(mx, __shfl_xor_sync(0xffffffffu,mx,o));
        float sum = 0.f;
        #pragma unroll
        for(int k=0;k<8;k++){ vals[k] = __expf(vals[k]-mx); sum += vals[k]; }
        #pragma unroll
        for(int o=16;o;o>>=1) sum += __shfl_xor_sync(0xffffffffu,sum,o);
        float inv = 1.0f/sum;
        #pragma unroll
        for(int k=0;k<8;k++) sc[w*256 + l + 32*k] = vals[k]*inv;
    }
    __syncthreads();

    // ---- phase 2a: t[h][c] = sum_j w[h][j]*tm[j][c]  (thread owns (h,c)+(h+2,c)) ----
    {
        int h = t>>7; int c = t&127; int hB = h+2;
        float ta=0.f, tb=0.f;
        const float4* wa4=(const float4*)(sc + h*256);
        const float4* wb4=(const float4*)(sc + hB*256);
        for(int jq=0;jq<njq;jq++){
            float4 wa=wa4[jq], wb=wb4[jq];
            const float* tp = tm_s + jq*512 + c;
            float t0=tp[0], t1=tp[128], t2=tp[256], t3=tp[384];
            ta += wa.x*t0 + wa.y*t1 + wa.z*t2 + wa.w*t3;
            tb += wb.x*t0 + wb.y*t1 + wb.z*t2 + wb.w*t3;
        }
        t_s[h*128+c]=ta; t_s[hB*128+c]=tb;
    }
    __syncthreads();

    // ---- phase 2b: out = w@V + WA2_h @ t ; residual with qln ----
    if(t<128){
        int e=t, h=e>>5;
        const float4* wr4 = (const float4*)(sc + h*256);
        const float* Vb = Vp + (((size_t)b<<8))*128 + e;
        float ov=0.f;
        for(int jq=0;jq<njq;jq++){
            float4 ww = wr4[jq];
            const float* vp = Vb + jq*512;
            ov += ww.x*vp[0] + ww.y*vp[128] + ww.z*vp[256] + ww.w*vp[384];
        }
        float acc = ov;
        const float4* w2 = (const float4*)(Wa2 + (size_t)e*128);
        const float4* th = (const float4*)(t_s + h*128);
        #pragma unroll
        for(int cq=0;cq<32;cq++){
            float4 a=w2[cq], tv=th[cq];
            acc += a.x*tv.x + a.y*tv.y + a.z*tv.z + a.w*tv.w;
        }
        xo[(size_t)r*128+e] = qln[(size_t)r*128+e] + acc;
    }
}

// ---------------- FFN: relu(x@W1^T+b1)@W2^T + b2 + x, * keep ----------------
__global__ void __launch_bounds__(256) k_ffn(
    const float* __restrict__ y,
    const float* __restrict__ W1, const float* __restrict__ b1,
    const float* __restrict__ W2, const float* __restrict__ b2,
    const unsigned char* __restrict__ msk, float* __restrict__ xo)
{
    __shared__ float xs[16][128];
    __shared__ float ps[16][128];
    __shared__ float hs[16][128];
    int t = threadIdx.x; int e = t & 127; int s = t >> 7;
    int r0 = blockIdx.x * 16;
    for(int k=t;k<2048;k+=256) xs[k>>7][k&127] = y[(size_t)r0*Hq + k];
    __syncthreads();

    float o16[16];
    mat16(xs, ps, W1, b1, e, s, o16);
    if(s==0){
        #pragma unroll
        for(int r=0;r<16;r++) hs[r][e] = fmaxf(o16[r], 0.f);
    }
    __syncthreads();
    mat16(hs, ps, W2, b2, e, s, o16);
    if(s==0){
        #pragma unroll
        for(int r=0;r<16;r++){
            int row = r0 + r;
            float kp = msk[row] ? 0.f : 1.f;
            xo[(size_t)row*Hq + e] = (o16[r] + xs[r][e]) * kp;
        }
    }
}

// ---------------- launch ----------------
extern "C" void kernel_launch(void* const* d_in, const int* in_sizes, int n_in,
                              void* d_out, int out_size){
    const float* seqs = (const float*)d_in[0];
    const unsigned char* msk = (const unsigned char*)d_in[1]; // all-false bool mask
    const float* tm  = (const float*)d_in[2];
    const float* Qw  = (const float*)d_in[3];
    const float* Qb  = (const float*)d_in[4];
    const float* Kw  = (const float*)d_in[5];
    const float* Kb  = (const float*)d_in[6];
    const float* Vw  = (const float*)d_in[7];
    const float* Vb  = (const float*)d_in[8];
    const float* WA1 = (const float*)d_in[9];
    const float* WA2 = (const float*)d_in[10];
    const float* ln1g= (const float*)d_in[11];
    const float* ln1b= (const float*)d_in[12];
    const float* ln2g= (const float*)d_in[13];
    const float* ln2b= (const float*)d_in[14];
    const float* c1w = (const float*)d_in[15];
    const float* c1b = (const float*)d_in[16];
    const float* c2w = (const float*)d_in[17];
    const float* c2b = (const float*)d_in[18];
    const float* lnfg= (const float*)d_in[19];
    const float* lnfb= (const float*)d_in[20];

    float *gqln,*gQ,*gK,*gV,*gu,*gatt,*gy,*gx;
    cudaGetSymbolAddress((void**)&gqln, g_qln);
    cudaGetSymbolAddress((void**)&gQ,   g_Q);
    cudaGetSymbolAddress((void**)&gK,   g_K);
    cudaGetSymbolAddress((void**)&gV,   g_V);
    cudaGetSymbolAddress((void**)&gu,   g_u);
    cudaGetSymbolAddress((void**)&gatt, g_att);
    cudaGetSymbolAddress((void**)&gy,   g_y);
    cudaGetSymbolAddress((void**)&gx,   g_x);

    cudaFuncSetAttribute(k_attn, cudaFuncAttributeMaxDynamicSharedMemorySize, ATTN_SMEM);

    for(int blk=0; blk<2; blk++){
        const float* xin = blk ? (const float*)gx : seqs;
        k_ln  <<<BLq,128>>>(xin, ln1g+blk*Hq, ln1b+blk*Hq, gqln);
        k_proj<<<128,256>>>(gqln,
                            Qw+(size_t)blk*HHq, Qb+blk*Hq,
                            Kw+(size_t)blk*HHq, Kb+blk*Hq,
                            Vw+(size_t)blk*HHq, Vb+blk*Hq,
                            WA1+(size_t)blk*HHq,
                            gQ, gK, gV, gu);
        k_attn<<<BLq,256,ATTN_SMEM>>>(tm, gqln, gQ, gK, gV, gu, msk,
                                      WA2+(size_t)blk*HHq, gatt);
        k_ln  <<<BLq,128>>>(gatt, ln2g+blk*Hq, ln2b+blk*Hq, gy);
        k_ffn <<<128,256>>>(gy, c1w+(size_t)blk*HHq, c1b+blk*Hq,
                            c2w+(size_t)blk*HHq, c2b+blk*Hq, msk, gx);
    }
    k_ln<<<BLq,128>>>(gx, lnfg, lnfb, (float*)d_out);
}

// round 4
// speedup vs baseline: 1.7781x; 1.7781x over previous
#include <cuda_runtime.h>
#include <cstdint>

#define Bq 8
#define Lq 256
#define Hq 128
#define BLq 2048
#define HHq 16384

// ---------------- scratch (no allocation allowed) ----------------
__device__ float g_qln[BLq*Hq];
__device__ float g_Q  [BLq*Hq];
__device__ float g_K  [BLq*Hq];
__device__ float g_V  [BLq*Hq];
__device__ float g_u  [BLq*4*Hq];
__device__ float g_att[BLq*Hq];
__device__ float g_x  [BLq*Hq];

// ---------------- helpers ----------------
__device__ __forceinline__ void cpa16(float* s, const float* g){
    unsigned sa = (unsigned)__cvta_generic_to_shared(s);
    asm volatile("cp.async.cg.shared.global [%0], [%1], 16;\n" :: "r"(sa), "l"(g));
}

// ---------------- final layernorm ----------------
__global__ void k_ln(const float* __restrict__ x, const float* __restrict__ g,
                     const float* __restrict__ bb, float* __restrict__ y){
    int r = blockIdx.x; int e = threadIdx.x;
    float v = x[(size_t)r*Hq + e];
    float s = v, s2 = v*v;
    #pragma unroll
    for(int o=16;o;o>>=1){
        s  += __shfl_xor_sync(0xffffffffu, s , o);
        s2 += __shfl_xor_sync(0xffffffffu, s2, o);
    }
    __shared__ float sh[8];
    int w = e>>5, l = e&31;
    if(l==0){ sh[w]=s; sh[4+w]=s2; }
    __syncthreads();
    s  = sh[0]+sh[1]+sh[2]+sh[3];
    s2 = sh[4]+sh[5]+sh[6]+sh[7];
    float m   = s * (1.0f/128.0f);
    float var = s2 * (1.0f/128.0f) - m*m;
    y[(size_t)r*Hq + e] = (v - m) * rsqrtf(var + 1e-8f) * g[e] + bb[e];
}

// ---------------- in-smem LN of a 16x128 row tile (8 warps, 2 rows each) ------
__device__ __forceinline__ void ln16(float xs[16][128], const float* __restrict__ g,
                                     const float* __restrict__ bb, int w, int l,
                                     float* __restrict__ sideout, int r0){
    #pragma unroll
    for(int rs=0;rs<2;rs++){
        int rr = w + rs*8;
        float v0=xs[rr][l], v1=xs[rr][l+32], v2=xs[rr][l+64], v3=xs[rr][l+96];
        float s  = v0+v1+v2+v3;
        float s2 = v0*v0+v1*v1+v2*v2+v3*v3;
        #pragma unroll
        for(int o=16;o;o>>=1){
            s  += __shfl_xor_sync(0xffffffffu, s , o);
            s2 += __shfl_xor_sync(0xffffffffu, s2, o);
        }
        float m   = s * (1.0f/128.0f);
        float inv = rsqrtf(s2*(1.0f/128.0f) - m*m + 1e-8f);
        float o0 = (v0-m)*inv*g[l]    + bb[l];
        float o1 = (v1-m)*inv*g[l+32] + bb[l+32];
        float o2 = (v2-m)*inv*g[l+64] + bb[l+64];
        float o3 = (v3-m)*inv*g[l+96] + bb[l+96];
        xs[rr][l]=o0; xs[rr][l+32]=o1; xs[rr][l+64]=o2; xs[rr][l+96]=o3;
        if(sideout){
            float* dst = sideout + (size_t)(r0+rr)*Hq;
            dst[l]=o0; dst[l+32]=o1; dst[l+64]=o2; dst[l+96]=o3;
        }
    }
}

// ---------------- 16-row tiled GEMM helper ----------------
__device__ __forceinline__ void mat16(const float xs[16][128], float ps[16][128],
                                      const float* __restrict__ W, const float* __restrict__ bias,
                                      int e, int s, float out[16]){
    float acc[16];
    #pragma unroll
    for(int r=0;r<16;r++) acc[r]=0.f;
    const float4* wq = (const float4*)(W + (size_t)e*128 + s*64);
    #pragma unroll
    for(int cq=0;cq<16;cq++){
        float4 wv = wq[cq];
        #pragma unroll
        for(int r=0;r<16;r++){
            float4 xv = *(const float4*)(&xs[r][s*64 + cq*4]);
            acc[r] += wv.x*xv.x + wv.y*xv.y + wv.z*xv.z + wv.w*xv.w;
        }
    }
    if(s==1){
        #pragma unroll
        for(int r=0;r<16;r++) ps[r][e]=acc[r];
    }
    __syncthreads();
    if(s==0){
        float be = bias[e];
        #pragma unroll
        for(int r=0;r<16;r++) out[r] = acc[r] + ps[r][e] + be;
    }
}

// ---------------- k_proj: LN1 fused + Q,K,V + u = WA1_h^T Q_h ----------------
__global__ void __launch_bounds__(256) k_proj(
    const float* __restrict__ xin,
    const float* __restrict__ g1, const float* __restrict__ b1,
    const float* __restrict__ Wq, const float* __restrict__ bq,
    const float* __restrict__ Wk, const float* __restrict__ bk,
    const float* __restrict__ Wv, const float* __restrict__ bv,
    const float* __restrict__ Wa1,
    float* __restrict__ qlno,
    float* __restrict__ Qo, float* __restrict__ Ko, float* __restrict__ Vo,
    float* __restrict__ uo)
{
    __shared__ float xs[16][128];
    __shared__ float ps[16][128];
    __shared__ float Qs[16][128];
    int t = threadIdx.x; int e = t & 127; int s = t >> 7;
    int l = t & 31;    int w = t >> 5;
    int r0 = blockIdx.x * 16;
    for(int k=t;k<2048;k+=256) xs[k>>7][k&127] = xin[(size_t)r0*Hq + k];
    __syncthreads();
    ln16(xs, g1, b1, w, l, qlno, r0);
    __syncthreads();

    float o16[16];
    mat16(xs, ps, Wq, bq, e, s, o16);
    if(s==0){
        #pragma unroll
        for(int r=0;r<16;r++){ float v=o16[r]; Qo[(size_t)(r0+r)*Hq+e]=v; Qs[r][e]=v; }
    }
    __syncthreads();
    mat16(xs, ps, Wk, bk, e, s, o16);
    if(s==0){
        #pragma unroll
        for(int r=0;r<16;r++) Ko[(size_t)(r0+r)*Hq+e]=o16[r];
    }
    __syncthreads();
    mat16(xs, ps, Wv, bv, e, s, o16);
    if(s==0){
        #pragma unroll
        for(int r=0;r<16;r++) Vo[(size_t)(r0+r)*Hq+e]=o16[r];
    }
    __syncthreads();

    // u[row][h][c] = sum_d WA1[h*32+d, c] * Q[row, h*32+d]
    int h = t>>6, c0 = t&63;
    float a0[16], a1[16];
    #pragma unroll
    for(int r=0;r<16;r++){ a0[r]=0.f; a1[r]=0.f; }
    for(int d=0; d<32; d++){
        const float* wr = Wa1 + (size_t)(h*32+d)*128;
        float w0 = wr[c0], w1 = wr[c0+64];
        #pragma unroll
        for(int r=0;r<16;r++){
            float q = Qs[r][h*32+d];
            a0[r] += w0*q; a1[r] += w1*q;
        }
    }
    #pragma unroll
    for(int r=0;r<16;r++){
        size_t base = ((size_t)(r0+r)*4 + h)*128;
        uo[base + c0]      = a0[r];
        uo[base + c0 + 64] = a1[r];
    }
}

// ---------------- fused flash-style attention: one CTA per (b,i) ----------------
// smem: buf 2x(64x128) | sc_raw 256 | sc_w 256 | t_s 512 | alph 4 | sinv 4
#define ATTN_FLOATS (16384 + 256 + 256 + 512 + 8)
#define ATTN_SMEM (ATTN_FLOATS*4)
__global__ void __launch_bounds__(256) k_attn(
    const float* __restrict__ tm,  const float* __restrict__ qln,
    const float* __restrict__ Qp,  const float* __restrict__ Kp,
    const float* __restrict__ Vp,  const float* __restrict__ up,
    const unsigned char* __restrict__ msk,
    const float* __restrict__ Wa2, float* __restrict__ xo)
{
    extern __shared__ float sm[];
    float* sc_raw = sm + 16384;
    float* sc_w   = sm + 16640;
    float* t_s    = sm + 16896;
    float* alph   = sm + 17408;
    float* sinv   = sm + 17412;

    int t = threadIdx.x, l = t&31, w = t>>5;
    int r = blockIdx.x, b = r>>8;
    int i = 255 - (r & 255);          // big rows first (tail balance)
    int rr = (b<<8) + i;
    bool rowmask = msk[rr] != 0;
    int nj  = rowmask ? 256 : (i+1);
    int nch = (nj + 63) >> 6;

    // issue chunk 0
    {
        float* dst = sm;
        int jn = nj < 64 ? nj : 64;
        const float* src = tm + (size_t)rr*32768;
        int n4 = jn*32;
        for(int k=t;k<n4;k+=256) cpa16(dst + 4*k, src + 4*k);
        int padf = (64-jn)*128;
        for(int k=t;k<padf;k+=256) dst[jn*128+k]=0.f;
    }
    asm volatile("cp.async.commit_group;\n"::);

    // preload per-row vectors (overlaps with cp.async)
    float4 uv0,uv1,uv2,uv3; float qv0,qv1,qv2,qv3;
    {
        const float4* ub = (const float4*)(up + (size_t)rr*512);
        uv0 = ub[l]; uv1 = ub[32+l]; uv2 = ub[64+l]; uv3 = ub[96+l];
        const float* Qr = Qp + (size_t)rr*128;
        qv0 = Qr[l]; qv1 = Qr[32+l]; qv2 = Qr[64+l]; qv3 = Qr[96+l];
    }

    float tA=0.f, tB=0.f, oA=0.f;
    const float NINF = -3.402823466e38f;
    const float NEGV = -4294967295.0f;
    float m_run = NINF, s_run = 0.f;
    int hT = t>>7, cT = t&127;          // t-accumulator ownership
    int eO = t & 127, hO = eO>>5;       // o-accumulator ownership (t<128)

    for(int c=0;c<nch;c++){
        if(c+1 < nch){
            float* dst = sm + ((c+1)&1)*8192;
            int j0n = (c+1)<<6;
            int jn = nj - j0n; if(jn>64) jn=64;
            const float* src = tm + (size_t)rr*32768 + (size_t)j0n*128;
            int n4 = jn*32;
            for(int k=t;k<n4;k+=256) cpa16(dst + 4*k, src + 4*k);
            int padf = (64-jn)*128;
            for(int k=t;k<padf;k+=256) dst[jn*128+k]=0.f;
            asm volatile("cp.async.commit_group;\n"::);
            asm volatile("cp.async.wait_group 1;\n"::);
        } else {
            asm volatile("cp.async.wait_group 0;\n"::);
        }
        __syncthreads();
        const float* bufc = sm + (c&1)*8192;
        int j0 = c<<6;

        // ---- phase A: raw scores (warp per j) ----
        #pragma unroll
        for(int jj=w; jj<64; jj+=8){
            float4 tv = ((const float4*)(bufc + jj*128))[l];
            const float* Kr = Kp + (((size_t)b<<8) + (j0+jj))*128;
            float a0 = uv0.x*tv.x + uv0.y*tv.y + uv0.z*tv.z + uv0.w*tv.w + qv0*Kr[l];
            float a1 = uv1.x*tv.x + uv1.y*tv.y + uv1.z*tv.z + uv1.w*tv.w + qv1*Kr[32+l];
            float a2 = uv2.x*tv.x + uv2.y*tv.y + uv2.z*tv.z + uv2.w*tv.w + qv2*Kr[64+l];
            float a3 = uv3.x*tv.x + uv3.y*tv.y + uv3.z*tv.z + uv3.w*tv.w + qv3*Kr[96+l];
            #pragma unroll
            for(int o=16;o;o>>=1){
                a0 += __shfl_xor_sync(0xffffffffu,a0,o);
                a1 += __shfl_xor_sync(0xffffffffu,a1,o);
                a2 += __shfl_xor_sync(0xffffffffu,a2,o);
                a3 += __shfl_xor_sync(0xffffffffu,a3,o);
            }
            if(l<4) sc_raw[l*64 + jj] = (l==0)?a0:((l==1)?a1:((l==2)?a2:a3));
        }
        __syncthreads();

        // ---- phase B: online softmax update (warp w = head w) ----
        if(w<4){
            float s0 = sc_raw[w*64 + l]      * 0.17677669529663689f;
            float s1 = sc_raw[w*64 + 32 + l] * 0.17677669529663689f;
            bool v0 = ((j0 + l)      < nj) && !rowmask;
            bool v1 = ((j0 + 32 + l) < nj) && !rowmask;
            s0 = v0 ? s0 : NEGV;
            s1 = v1 ? s1 : NEGV;
            float mx = fmaxf(s0, s1);
            #pragma unroll
            for(int o=16;o;o>>=1) mx = fmaxf(mx, __shfl_xor_sync(0xffffffffu,mx,o));
            float mnew = fmaxf(m_run, mx);
            float alpha = __expf(m_run - mnew);
            float e0 = __expf(s0 - mnew), e1 = __expf(s1 - mnew);
            float cs = e0 + e1;
            #pragma unroll
            for(int o=16;o;o>>=1) cs += __shfl_xor_sync(0xffffffffu,cs,o);
            s_run = s_run*alpha + cs;
            m_run = mnew;
            sc_w[w*64 + l]      = e0;
            sc_w[w*64 + 32 + l] = e1;
            if(l==0) alph[w] = alpha;
        }
        __syncthreads();

        // ---- phase C: rescale + accumulate t and o ----
        {
            float aA = alph[hT], aB = alph[hT+2];
            tA *= aA; tB *= aB;
            const float4* wa4 = (const float4*)(sc_w + hT*64);
            const float4* wb4 = (const float4*)(sc_w + (hT+2)*64);
            const float* bp = bufc + cT;
            #pragma unroll 4
            for(int jq=0;jq<16;jq++){
                float4 wa = wa4[jq], wb = wb4[jq];
                const float* tp = bp + jq*512;
                float t0=tp[0], t1=tp[128], t2=tp[256], t3=tp[384];
                tA += wa.x*t0 + wa.y*t1 + wa.z*t2 + wa.w*t3;
                tB += wb.x*t0 + wb.y*t1 + wb.z*t2 + wb.w*t3;
            }
        }
        if(t<128){
            oA *= alph[hO];
            const float4* wr4 = (const float4*)(sc_w + hO*64);
            const float* Vb = Vp + ((((size_t)b<<8) + j0))*128 + eO;
            #pragma unroll 4
            for(int jq=0;jq<16;jq++){
                float4 ww = wr4[jq];
                const float* vp = Vb + jq*512;
                oA += ww.x*vp[0] + ww.y*vp[128] + ww.z*vp[256] + ww.w*vp[384];
            }
        }
        __syncthreads();
    }

    if(w<4 && l==0) sinv[w] = 1.0f / s_run;
    __syncthreads();
    t_s[hT*128 + cT]     = tA * sinv[hT];
    t_s[(hT+2)*128 + cT] = tB * sinv[hT+2];
    __syncthreads();
    if(t<128){
        float acc = oA * sinv[hO];
        const float4* w2 = (const float4*)(Wa2 + (size_t)eO*128);
        const float4* th = (const float4*)(t_s + hO*128);
        #pragma unroll
        for(int cq=0;cq<32;cq++){
            float4 a=w2[cq], tv=th[cq];
            acc += a.x*tv.x + a.y*tv.y + a.z*tv.z + a.w*tv.w;
        }
        xo[(size_t)rr*128 + eO] = qln[(size_t)rr*128 + eO] + acc;
    }
}

// ---------------- k_ffn: LN2 fused + relu(x@W1^T+b1)@W2^T + b2 + x, * keep ----
__global__ void __launch_bounds__(256) k_ffn(
    const float* __restrict__ attin,
    const float* __restrict__ g2, const float* __restrict__ b2g,
    const float* __restrict__ W1, const float* __restrict__ b1,
    const float* __restrict__ W2, const float* __restrict__ b2,
    const unsigned char* __restrict__ msk, float* __restrict__ xo)
{
    __shared__ float xs[16][128];
    __shared__ float ps[16][128];
    __shared__ float hs[16][128];
    int t = threadIdx.x; int e = t & 127; int s = t >> 7;
    int l = t & 31;    int w = t >> 5;
    int r0 = blockIdx.x * 16;
    for(int k=t;k<2048;k+=256) xs[k>>7][k&127] = attin[(size_t)r0*Hq + k];
    __syncthreads();
    ln16(xs, g2, b2g, w, l, (float*)0, r0);
    __syncthreads();

    float o16[16];
    mat16(xs, ps, W1, b1, e, s, o16);
    if(s==0){
        #pragma unroll
        for(int r=0;r<16;r++) hs[r][e] = fmaxf(o16[r], 0.f);
    }
    __syncthreads();
    mat16(hs, ps, W2, b2, e, s, o16);
    if(s==0){
        #pragma unroll
        for(int r=0;r<16;r++){
            int row = r0 + r;
            float kp = msk[row] ? 0.f : 1.f;
            xo[(size_t)row*Hq + e] = (o16[r] + xs[r][e]) * kp;
        }
    }
}

// ---------------- launch ----------------
extern "C" void kernel_launch(void* const* d_in, const int* in_sizes, int n_in,
                              void* d_out, int out_size){
    const float* seqs = (const float*)d_in[0];
    const unsigned char* msk = (const unsigned char*)d_in[1];
    const float* tm  = (const float*)d_in[2];
    const float* Qw  = (const float*)d_in[3];
    const float* Qb  = (const float*)d_in[4];
    const float* Kw  = (const float*)d_in[5];
    const float* Kb  = (const float*)d_in[6];
    const float* Vw  = (const float*)d_in[7];
    const float* Vb  = (const float*)d_in[8];
    const float* WA1 = (const float*)d_in[9];
    const float* WA2 = (const float*)d_in[10];
    const float* ln1g= (const float*)d_in[11];
    const float* ln1b= (const float*)d_in[12];
    const float* ln2g= (const float*)d_in[13];
    const float* ln2b= (const float*)d_in[14];
    const float* c1w = (const float*)d_in[15];
    const float* c1b = (const float*)d_in[16];
    const float* c2w = (const float*)d_in[17];
    const float* c2b = (const float*)d_in[18];
    const float* lnfg= (const float*)d_in[19];
    const float* lnfb= (const float*)d_in[20];

    float *gqln,*gQ,*gK,*gV,*gu,*gatt,*gx;
    cudaGetSymbolAddress((void**)&gqln, g_qln);
    cudaGetSymbolAddress((void**)&gQ,   g_Q);
    cudaGetSymbolAddress((void**)&gK,   g_K);
    cudaGetSymbolAddress((void**)&gV,   g_V);
    cudaGetSymbolAddress((void**)&gu,   g_u);
    cudaGetSymbolAddress((void**)&gatt, g_att);
    cudaGetSymbolAddress((void**)&gx,   g_x);

    cudaFuncSetAttribute(k_attn, cudaFuncAttributeMaxDynamicSharedMemorySize, ATTN_SMEM);

    for(int blk=0; blk<2; blk++){
        const float* xin = blk ? (const float*)gx : seqs;
        k_proj<<<128,256>>>(xin, ln1g+blk*Hq, ln1b+blk*Hq,
                            Qw+(size_t)blk*HHq, Qb+blk*Hq,
                            Kw+(size_t)blk*HHq, Kb+blk*Hq,
                            Vw+(size_t)blk*HHq, Vb+blk*Hq,
                            WA1+(size_t)blk*HHq,
                            gqln, gQ, gK, gV, gu);
        k_attn<<<BLq,256,ATTN_SMEM>>>(tm, gqln, gQ, gK, gV, gu, msk,
                                      WA2+(size_t)blk*HHq, gatt);
        k_ffn <<<128,256>>>(gatt, ln2g+blk*Hq, ln2b+blk*Hq,
                            c1w+(size_t)blk*HHq, c1b+blk*Hq,
                            c2w+(size_t)blk*HHq, c2b+blk*Hq, msk, gx);
    }
    k_ln<<<BLq,128>>>(gx, lnfg, lnfb, (float*)d_out);
}